// round 6
// baseline (speedup 1.0000x reference)
#include <cuda_runtime.h>
#include <cuda_bf16.h>
#include <cstdint>

#define BB 64
#define TT 2048
#define MM 512
#define PP 512

// Device scratch
__device__ float g_dsp[BB * MM];
__device__ float g_part[8 * BB * MM];
__device__ __nv_bfloat16 g_UT[MM * MM];          // U_d^T [n][k], bf16
__device__ float g_l[BB * TT];

__device__ __forceinline__ float tanh_fast(float x) {
    float y;
    asm("tanh.approx.f32 %0, %1;" : "=f"(y) : "f"(x));
    return y;
}
__device__ __forceinline__ void cp_async16(uint32_t dst, const void* src) {
    asm volatile("cp.async.cg.shared.global [%0], [%1], 16;" :: "r"(dst), "l"(src) : "memory");
}
__device__ __forceinline__ void cp_commit() {
    asm volatile("cp.async.commit_group;" ::: "memory");
}
__device__ __forceinline__ void cp_wait1() {
    asm volatile("cp.async.wait_group 1;" ::: "memory");
}

#define SWZ16(r, c) (((r) << 10) + (((c) ^ ((r) & 7)) << 4))

// ---------------------------------------------------------------------------
// Kernel 2: g_UT[n][k] = bf16(U[k][n])   (launched FIRST; independent)
// ---------------------------------------------------------------------------
__global__ void k_transU(const float* __restrict__ U) {
    __shared__ float tile[32][33];
    int n0 = blockIdx.x * 32, k0 = blockIdx.y * 32;
    for (int i = threadIdx.y; i < 32; i += 8)
        tile[i][threadIdx.x] = U[(k0 + i) * MM + n0 + threadIdx.x];
    __syncthreads();
    for (int i = threadIdx.y; i < 32; i += 8)
        g_UT[(n0 + i) * MM + (k0 + threadIdx.x)] = __float2bfloat16(tile[threadIdx.x][i]);
}

// ---------------------------------------------------------------------------
// Kernel 1a: dsproj partials. grid = 16 bgrp x 8 kslab, 512 thr.
// ---------------------------------------------------------------------------
__global__ __launch_bounds__(512) void k_dsproj1(const float* __restrict__ h,
                                                 const float* __restrict__ c,
                                                 const float* __restrict__ W) {
    __shared__ float ds[4][128];
    int bgrp = blockIdx.x >> 3;
    int ks = blockIdx.x & 7;
    int tid = threadIdx.x;
    {
        int j = tid >> 7, kk = tid & 127;
        int k = ks * 128 + kk;
        float v = (k < PP) ? h[(bgrp * 4 + j) * PP + k]
                           : c[(bgrp * 4 + j) * PP + (k - PP)];
        ds[j][kk] = v;
    }
    __syncthreads();
    float a0 = 0.f, a1 = 0.f, a2 = 0.f, a3 = 0.f;
    const float* Wp = W + (ks * 128) * MM + tid;
#pragma unroll 8
    for (int kk = 0; kk < 128; kk++) {
        float w = Wp[kk * MM];
        a0 = fmaf(w, ds[0][kk], a0);
        a1 = fmaf(w, ds[1][kk], a1);
        a2 = fmaf(w, ds[2][kk], a2);
        a3 = fmaf(w, ds[3][kk], a3);
    }
    int base = (ks * BB + bgrp * 4) * MM + tid;
    g_part[base] = a0;
    g_part[base + MM] = a1;
    g_part[base + 2 * MM] = a2;
    g_part[base + 3 * MM] = a3;
}

// ---------------------------------------------------------------------------
// Kernel 1b: reduce partials + biases.
// ---------------------------------------------------------------------------
__global__ __launch_bounds__(512) void k_dsproj2(const float* __restrict__ bwd,
                                                 const float* __restrict__ bud) {
    int b = blockIdx.x, n = threadIdx.x;
    float s = bwd[n] + bud[n];
#pragma unroll
    for (int ks = 0; ks < 8; ks++)
        s += g_part[(ks * BB + b) * MM + n];
    g_dsp[b * MM + n] = s;
}

// ---------------------------------------------------------------------------
// Kernel 3: fused GEMM + tanh + v-dot, warp-specialized:
//  - warps 0-3 (COMPUTE): m64xn32 tiles, mma.sync bf16; per chunk dump acc
//    (bf16) to a staging buffer.
//  - warps 4-7 (LOADER): stream B via cp.async AND run the tanh/v-dot
//    epilogue for chunk nc-1 (from staging) DURING chunk nc's MMA phases.
//    Loader thread t owns t-row t -> writes g_l directly (no reductions).
// ---------------------------------------------------------------------------
#define A_OFF    0
#define B_OFF    131072
#define DSP_OFF  196608
#define V_OFF    198656
#define STG_OFF  200704
#define STG_PITCH 132
#define SMEM_TOTAL (STG_OFF + 128 * STG_PITCH)   // 217600

__global__ __launch_bounds__(256, 1) void k_main(const float* __restrict__ enc,
                                                 const float* __restrict__ vd) {
    extern __shared__ char sm[];
    uint32_t sbase = (uint32_t)__cvta_generic_to_shared(sm);
    uint32_t sA = sbase + A_OFF;
    uint32_t sB = sbase + B_OFF;
    float* dsp_s = (float*)(sm + DSP_OFF);
    float* v_s = (float*)(sm + V_OFF);
    char* stg = sm + STG_OFF;

    int blk = blockIdx.x;
    int b = blk >> 4;
    int t0 = (blk & 15) << 7;
    int tid = threadIdx.x;
    int lane = tid & 31;
    int wid = tid >> 5;
    int wm = wid & 1;
    int wn = (wid >> 1) & 1;
    int g = lane >> 2;
    int tig = lane & 3;

    const __nv_bfloat16* UT = &g_UT[0];

    auto loadBhalf = [&](int nc, int h) {
#pragma unroll
        for (int i = tid - 128; i < 2048; i += 128) {
            int r = i >> 5;
            int c = i & 31;
            cp_async16(sB + SWZ16(r, (h << 5) + c),
                       UT + ((nc << 6) + r) * MM + (h << 8) + (c << 3));
        }
    };

    // Prologue: loader warps queue both halves of B chunk 0
    if (tid >= 128) {
        loadBhalf(0, 0); cp_commit();
        loadBhalf(0, 1); cp_commit();
    }

    // Load A: 128 x 512 fp32 -> bf16 swizzled (all 256 threads)
    {
        const float4* src = (const float4*)(enc + (size_t)(b * TT + t0) * MM);
#pragma unroll 8
        for (int i = tid; i < 8192; i += 256) {
            int r = i >> 6;
            int c = i & 63;
            float4 f0 = src[(r << 7) + (c << 1)];
            float4 f1 = src[(r << 7) + (c << 1) + 1];
            __nv_bfloat162 p0 = __floats2bfloat162_rn(f0.x, f0.y);
            __nv_bfloat162 p1 = __floats2bfloat162_rn(f0.z, f0.w);
            __nv_bfloat162 p2 = __floats2bfloat162_rn(f1.x, f1.y);
            __nv_bfloat162 p3 = __floats2bfloat162_rn(f1.z, f1.w);
            uint4 u;
            u.x = *(uint32_t*)&p0; u.y = *(uint32_t*)&p1;
            u.z = *(uint32_t*)&p2; u.w = *(uint32_t*)&p3;
            *(uint4*)(sm + A_OFF + SWZ16(r, c)) = u;
        }
        for (int i = tid; i < MM; i += 256) {
            dsp_s[i] = g_dsp[b * MM + i];
            v_s[i] = vd[i];
        }
    }

    // ldmatrix lane-address components (compute warps)
    int aRowB = (wm << 6) + (lane & 15);
    int aCadd = (lane >> 4);
    int bQuad = lane >> 3;
    int bRowIn = lane & 7;
    int bCadd = bQuad & 1;
    int bBlkHalf = bQuad >> 1;
    int bN0 = (wn << 5) + (bBlkHalf << 3) + bRowIn;
    int bN1 = bN0 + 16;

    uint32_t af[2][4][4];
    uint32_t bfr[2][2][4];
    float acc[4][4][4];
    float lp = 0.f;                                  // loader threads: full row logit
    int lrow = tid - 128;                            // loader-owned t-row

    auto loadFrags = [&](int buf, int ks) {
#pragma unroll
        for (int mi = 0; mi < 4; mi++) {
            uint32_t addr = sA + SWZ16(aRowB + (mi << 4), (ks << 1) + aCadd);
            asm volatile("ldmatrix.sync.aligned.m8n8.x4.shared.b16 {%0,%1,%2,%3}, [%4];"
                         : "=r"(af[buf][mi][0]), "=r"(af[buf][mi][1]),
                           "=r"(af[buf][mi][2]), "=r"(af[buf][mi][3]) : "r"(addr));
        }
#pragma unroll
        for (int jp = 0; jp < 2; jp++) {
            uint32_t addr = sB + SWZ16(jp ? bN1 : bN0, (ks << 1) + bCadd);
            asm volatile("ldmatrix.sync.aligned.m8n8.x4.shared.b16 {%0,%1,%2,%3}, [%4];"
                         : "=r"(bfr[buf][jp][0]), "=r"(bfr[buf][jp][1]),
                           "=r"(bfr[buf][jp][2]), "=r"(bfr[buf][jp][3]) : "r"(addr));
        }
    };

    // Loader epilogue: chunk cc, 32 cols starting at c0 (reads staging)
    auto epi32 = [&](int cc, int c0) {
#pragma unroll
        for (int jj = 0; jj < 16; jj++) {
            int c = c0 + (jj << 1);
            uint32_t w = *(uint32_t*)(stg + lrow * STG_PITCH + (c << 1));
            __nv_bfloat162 p = *(__nv_bfloat162*)&w;
            int col = (cc << 6) + c;
            float x0 = __bfloat162float(p.x) + dsp_s[col];
            float x1 = __bfloat162float(p.y) + dsp_s[col + 1];
            lp = fmaf(v_s[col], tanh_fast(x0), lp);
            lp = fmaf(v_s[col + 1], tanh_fast(x1), lp);
        }
    };

    for (int nc = 0; nc < 8; nc++) {
        if (tid < 128) {
#pragma unroll
            for (int mi = 0; mi < 4; mi++)
#pragma unroll
                for (int j = 0; j < 4; j++)
#pragma unroll
                    for (int q = 0; q < 4; q++) acc[mi][j][q] = 0.f;
        }

#pragma unroll
        for (int h = 0; h < 2; h++) {
            if (tid >= 128) cp_wait1();
            __syncthreads();             // B(nc,h) ready; stage(nc-1) visible

            if (tid < 128) {
                int kbase = h << 4;
                loadFrags(0, kbase);
#pragma unroll
                for (int kk = 0; kk < 16; kk++) {
                    int cur = kk & 1;
                    if (kk < 15) loadFrags(cur ^ 1, kbase + kk + 1);
#pragma unroll
                    for (int mi = 0; mi < 4; mi++)
#pragma unroll
                        for (int jp = 0; jp < 2; jp++) {
                            asm volatile("mma.sync.aligned.m16n8k16.row.col.f32.bf16.bf16.f32 "
                                "{%0,%1,%2,%3}, {%4,%5,%6,%7}, {%8,%9}, {%0,%1,%2,%3};"
                                : "+f"(acc[mi][jp * 2][0]), "+f"(acc[mi][jp * 2][1]),
                                  "+f"(acc[mi][jp * 2][2]), "+f"(acc[mi][jp * 2][3])
                                : "r"(af[cur][mi][0]), "r"(af[cur][mi][1]),
                                  "r"(af[cur][mi][2]), "r"(af[cur][mi][3]),
                                  "r"(bfr[cur][jp][0]), "r"(bfr[cur][jp][1]));
                            asm volatile("mma.sync.aligned.m16n8k16.row.col.f32.bf16.bf16.f32 "
                                "{%0,%1,%2,%3}, {%4,%5,%6,%7}, {%8,%9}, {%0,%1,%2,%3};"
                                : "+f"(acc[mi][jp * 2 + 1][0]), "+f"(acc[mi][jp * 2 + 1][1]),
                                  "+f"(acc[mi][jp * 2 + 1][2]), "+f"(acc[mi][jp * 2 + 1][3])
                                : "r"(af[cur][mi][0]), "r"(af[cur][mi][1]),
                                  "r"(af[cur][mi][2]), "r"(af[cur][mi][3]),
                                  "r"(bfr[cur][jp][2]), "r"(bfr[cur][jp][3]));
                        }
                }
            } else {
                if (nc > 0) epi32(nc - 1, h << 5);   // overlapped with MMA
            }
            __syncthreads();             // B(nc,h) consumed; stage reads done (h=1)

            if (tid >= 128) {
                int ph = (nc << 1) + h;
                if (ph < 14) loadBhalf((ph + 2) >> 1, (ph + 2) & 1);
                cp_commit();
            }
        }

        // Compute warps: dump chunk nc accumulators to staging (bf16)
        if (tid < 128) {
            int cbase = (wn << 5) + (tig << 1);
#pragma unroll
            for (int mi = 0; mi < 4; mi++) {
                int rA = (wm << 6) + (mi << 4) + g;
#pragma unroll
                for (int j = 0; j < 4; j++) {
                    int c = cbase + (j << 3);
                    __nv_bfloat162 pA = __floats2bfloat162_rn(acc[mi][j][0], acc[mi][j][1]);
                    __nv_bfloat162 pB = __floats2bfloat162_rn(acc[mi][j][2], acc[mi][j][3]);
                    *(uint32_t*)(stg + rA * STG_PITCH + (c << 1)) = *(uint32_t*)&pA;
                    *(uint32_t*)(stg + (rA + 8) * STG_PITCH + (c << 1)) = *(uint32_t*)&pB;
                }
            }
        }
    }

    __syncthreads();                     // stage(7) written
    if (tid >= 128) {
        epi32(7, 0);
        epi32(7, 32);
        g_l[b * TT + t0 + lrow] = lp;
    }
}

// ---------------------------------------------------------------------------
// Kernel 4: softmax over T per batch
// ---------------------------------------------------------------------------
__global__ void k_softmax(float* __restrict__ out) {
    __shared__ float red[8];
    int b = blockIdx.x, tid = threadIdx.x, lane = tid & 31, wid = tid >> 5;
    float vals[8];
    float m = -1e30f;
#pragma unroll
    for (int i = 0; i < 8; i++) {
        vals[i] = g_l[b * TT + i * 256 + tid];
        m = fmaxf(m, vals[i]);
    }
#pragma unroll
    for (int o = 16; o; o >>= 1) m = fmaxf(m, __shfl_xor_sync(0xffffffffu, m, o));
    if (lane == 0) red[wid] = m;
    __syncthreads();
    m = red[0];
#pragma unroll
    for (int i = 1; i < 8; i++) m = fmaxf(m, red[i]);
    __syncthreads();
    float s = 0.f;
#pragma unroll
    for (int i = 0; i < 8; i++) {
        vals[i] = __expf(vals[i] - m);
        s += vals[i];
    }
#pragma unroll
    for (int o = 16; o; o >>= 1) s += __shfl_xor_sync(0xffffffffu, s, o);
    if (lane == 0) red[wid] = s;
    __syncthreads();
    s = 0.f;
#pragma unroll
    for (int i = 0; i < 8; i++) s += red[i];
    float inv = 1.0f / s;
#pragma unroll
    for (int i = 0; i < 8; i++) out[b * TT + i * 256 + tid] = vals[i] * inv;
}

// ---------------------------------------------------------------------------
extern "C" void kernel_launch(void* const* d_in, const int* in_sizes, int n_in,
                              void* d_out, int out_size) {
    const float* h   = (const float*)d_in[0];
    const float* c   = (const float*)d_in[1];
    const float* enc = (const float*)d_in[2];
    const float* W   = (const float*)d_in[3];
    const float* bwd = (const float*)d_in[4];
    const float* U   = (const float*)d_in[5];
    const float* bud = (const float*)d_in[6];
    const float* vd  = (const float*)d_in[7];
    float* out = (float*)d_out;

    cudaFuncSetAttribute(k_main, cudaFuncAttributeMaxDynamicSharedMemorySize, SMEM_TOTAL);

    // k_main is the 4th launch -> lands in the ncu capture slot
    k_transU<<<dim3(16, 16), dim3(32, 8)>>>(U);
    k_dsproj1<<<128, 512>>>(h, c, W);
    k_dsproj2<<<64, 512>>>(bwd, bud);
    k_main<<<(BB * TT) / 128, 256, SMEM_TOTAL>>>(enc, vd);
    k_softmax<<<BB, 256>>>(out);
}

// round 7
// speedup vs baseline: 1.0402x; 1.0402x over previous
#include <cuda_runtime.h>
#include <cuda_bf16.h>
#include <cstdint>

#define BB 64
#define TT 2048
#define MM 512
#define PP 512

// Device scratch
__device__ float g_dsp[BB * MM];
__device__ float g_part[8 * BB * MM];
__device__ __nv_bfloat16 g_UT[MM * MM];          // U_d^T [n][k], bf16
__device__ float g_l[BB * TT];

__device__ __forceinline__ float tanh_fast(float x) {
    float y;
    asm("tanh.approx.f32 %0, %1;" : "=f"(y) : "f"(x));
    return y;
}
__device__ __forceinline__ void cp_async16(uint32_t dst, const void* src) {
    asm volatile("cp.async.cg.shared.global [%0], [%1], 16;" :: "r"(dst), "l"(src) : "memory");
}
__device__ __forceinline__ void cp_commit() {
    asm volatile("cp.async.commit_group;" ::: "memory");
}
__device__ __forceinline__ void cp_wait1() {
    asm volatile("cp.async.wait_group 1;" ::: "memory");
}

#define SWZ16(r, c) (((r) << 10) + (((c) ^ ((r) & 7)) << 4))

// ---------------------------------------------------------------------------
// Kernel 2: g_UT[n][k] = bf16(U[k][n])   (first launch; independent)
// ---------------------------------------------------------------------------
__global__ void k_transU(const float* __restrict__ U) {
    __shared__ float tile[32][33];
    int n0 = blockIdx.x * 32, k0 = blockIdx.y * 32;
    for (int i = threadIdx.y; i < 32; i += 8)
        tile[i][threadIdx.x] = U[(k0 + i) * MM + n0 + threadIdx.x];
    __syncthreads();
    for (int i = threadIdx.y; i < 32; i += 8)
        g_UT[(n0 + i) * MM + (k0 + threadIdx.x)] = __float2bfloat16(tile[threadIdx.x][i]);
}

// ---------------------------------------------------------------------------
// Kernel 1a: dsproj partials. grid = 16 bgrp x 8 kslab, 512 thr.
// ---------------------------------------------------------------------------
__global__ __launch_bounds__(512) void k_dsproj1(const float* __restrict__ h,
                                                 const float* __restrict__ c,
                                                 const float* __restrict__ W) {
    __shared__ float ds[4][128];
    int bgrp = blockIdx.x >> 3;
    int ks = blockIdx.x & 7;
    int tid = threadIdx.x;
    {
        int j = tid >> 7, kk = tid & 127;
        int k = ks * 128 + kk;
        float v = (k < PP) ? h[(bgrp * 4 + j) * PP + k]
                           : c[(bgrp * 4 + j) * PP + (k - PP)];
        ds[j][kk] = v;
    }
    __syncthreads();
    float a0 = 0.f, a1 = 0.f, a2 = 0.f, a3 = 0.f;
    const float* Wp = W + (ks * 128) * MM + tid;
#pragma unroll 8
    for (int kk = 0; kk < 128; kk++) {
        float w = Wp[kk * MM];
        a0 = fmaf(w, ds[0][kk], a0);
        a1 = fmaf(w, ds[1][kk], a1);
        a2 = fmaf(w, ds[2][kk], a2);
        a3 = fmaf(w, ds[3][kk], a3);
    }
    int base = (ks * BB + bgrp * 4) * MM + tid;
    g_part[base] = a0;
    g_part[base + MM] = a1;
    g_part[base + 2 * MM] = a2;
    g_part[base + 3 * MM] = a3;
}

// ---------------------------------------------------------------------------
// Kernel 1b: reduce partials + biases.
// ---------------------------------------------------------------------------
__global__ __launch_bounds__(512) void k_dsproj2(const float* __restrict__ bwd,
                                                 const float* __restrict__ bud) {
    int b = blockIdx.x, n = threadIdx.x;
    float s = bwd[n] + bud[n];
#pragma unroll
    for (int ks = 0; ks < 8; ks++)
        s += g_part[(ks * BB + b) * MM + n];
    g_dsp[b * MM + n] = s;
}

// ---------------------------------------------------------------------------
// Kernel 3 (round-3 proven design, 230us): fused GEMM + tanh + v-dot.
// CTA = 128 t-rows x N512 x K512, A (128x512 bf16) resident in SMEM.
// 8 compute warps, 4m x 2n grid (warp = m32 x n32 per n64 chunk).
// B streamed in 8 n64-chunks, each as two k-half waves through disjoint
// halves of one 64KB buffer (cp.async wait_group 1). Inner ks loop
// double-buffers ldmatrix fragments. Inline per-chunk tanh epilogue.
// ---------------------------------------------------------------------------
#define A_OFF    0
#define B_OFF    131072
#define DSP_OFF  196608
#define V_OFF    198656
#define PART_OFF 200704
#define SMEM_TOTAL 201280

__global__ __launch_bounds__(256, 1) void k_main(const float* __restrict__ enc,
                                                 const float* __restrict__ vd) {
    extern __shared__ char sm[];
    uint32_t sbase = (uint32_t)__cvta_generic_to_shared(sm);
    uint32_t sA = sbase + A_OFF;
    uint32_t sB = sbase + B_OFF;
    float* dsp_s = (float*)(sm + DSP_OFF);
    float* v_s = (float*)(sm + V_OFF);
    float* part = (float*)(sm + PART_OFF);

    int blk = blockIdx.x;
    int b = blk >> 4;
    int t0 = (blk & 15) << 7;
    int tid = threadIdx.x;
    int lane = tid & 31;
    int wid = tid >> 5;
    int wm = wid & 3;
    int wn = wid >> 2;
    int g = lane >> 2;
    int tig = lane & 3;

    const __nv_bfloat16* UT = &g_UT[0];

    // B half-chunk loader: chunk nc, k-half h (chunk cols h*32..h*32+31)
    auto loadBhalf = [&](int nc, int h) {
        const __nv_bfloat16* srcB = UT + (nc << 6) * MM;
        int cadd = h << 5;
#pragma unroll
        for (int i = tid; i < 2048; i += 256) {
            int r = i >> 5;
            int c = (i & 31) + cadd;
            cp_async16(sB + SWZ16(r, c), srcB + (r << 9) + (c << 3));
        }
    };

    // Prologue: queue both k-halves of B chunk 0 (overlap with A load)
    loadBhalf(0, 0); cp_commit();
    loadBhalf(0, 1); cp_commit();

    // Load A tile: 128 x 512 fp32 -> bf16, XOR-swizzled 1024B rows
    {
        const float4* src = (const float4*)(enc + (size_t)(b * TT + t0) * MM);
#pragma unroll 8
        for (int i = tid; i < 8192; i += 256) {
            int r = i >> 6;
            int c = i & 63;
            float4 f0 = src[(r << 7) + (c << 1)];
            float4 f1 = src[(r << 7) + (c << 1) + 1];
            __nv_bfloat162 p0 = __floats2bfloat162_rn(f0.x, f0.y);
            __nv_bfloat162 p1 = __floats2bfloat162_rn(f0.z, f0.w);
            __nv_bfloat162 p2 = __floats2bfloat162_rn(f1.x, f1.y);
            __nv_bfloat162 p3 = __floats2bfloat162_rn(f1.z, f1.w);
            uint4 u;
            u.x = *(uint32_t*)&p0; u.y = *(uint32_t*)&p1;
            u.z = *(uint32_t*)&p2; u.w = *(uint32_t*)&p3;
            *(uint4*)(sm + A_OFF + SWZ16(r, c)) = u;
        }
        for (int i = tid; i < MM; i += 256) {
            dsp_s[i] = g_dsp[b * MM + i];
            v_s[i] = vd[i];
        }
    }

    float lp[4] = {0.f, 0.f, 0.f, 0.f};

    // ldmatrix lane-address components
    int aRow0 = (wm << 5) + (lane & 15);
    int aRow1 = aRow0 + 16;
    int aCadd = (lane >> 4);
    int bQuad = lane >> 3;
    int bRowIn = lane & 7;
    int bCadd = bQuad & 1;
    int bBlkHalf = bQuad >> 1;
    int bN0 = (wn << 5) + (bBlkHalf << 3) + bRowIn;
    int bN1 = bN0 + 16;

    uint32_t af[2][2][4];
    uint32_t bfr[2][2][4];

    auto loadFrags = [&](int buf, int ks) {
#pragma unroll
        for (int mi = 0; mi < 2; mi++) {
            int r = mi ? aRow1 : aRow0;
            uint32_t addr = sA + SWZ16(r, (ks << 1) + aCadd);
            asm volatile("ldmatrix.sync.aligned.m8n8.x4.shared.b16 {%0,%1,%2,%3}, [%4];"
                         : "=r"(af[buf][mi][0]), "=r"(af[buf][mi][1]),
                           "=r"(af[buf][mi][2]), "=r"(af[buf][mi][3]) : "r"(addr));
        }
#pragma unroll
        for (int jp = 0; jp < 2; jp++) {
            int n = jp ? bN1 : bN0;
            uint32_t addr = sB + SWZ16(n, (ks << 1) + bCadd);
            asm volatile("ldmatrix.sync.aligned.m8n8.x4.shared.b16 {%0,%1,%2,%3}, [%4];"
                         : "=r"(bfr[buf][jp][0]), "=r"(bfr[buf][jp][1]),
                           "=r"(bfr[buf][jp][2]), "=r"(bfr[buf][jp][3]) : "r"(addr));
        }
    };

    float acc[2][4][4];

    for (int nc = 0; nc < 8; nc++) {
#pragma unroll
        for (int mi = 0; mi < 2; mi++)
#pragma unroll
            for (int j = 0; j < 4; j++)
#pragma unroll
                for (int q = 0; q < 4; q++) acc[mi][j][q] = 0.f;

#pragma unroll
        for (int h = 0; h < 2; h++) {
            cp_wait1();
            __syncthreads();                    // B half (nc,h) ready
            int kbase = h << 4;

            loadFrags(0, kbase);
#pragma unroll
            for (int kk = 0; kk < 16; kk++) {
                int cur = kk & 1;
                if (kk < 15) loadFrags(cur ^ 1, kbase + kk + 1);
#pragma unroll
                for (int mi = 0; mi < 2; mi++)
#pragma unroll
                    for (int jp = 0; jp < 2; jp++) {
                        asm volatile("mma.sync.aligned.m16n8k16.row.col.f32.bf16.bf16.f32 "
                            "{%0,%1,%2,%3}, {%4,%5,%6,%7}, {%8,%9}, {%0,%1,%2,%3};"
                            : "+f"(acc[mi][jp * 2][0]), "+f"(acc[mi][jp * 2][1]),
                              "+f"(acc[mi][jp * 2][2]), "+f"(acc[mi][jp * 2][3])
                            : "r"(af[cur][mi][0]), "r"(af[cur][mi][1]),
                              "r"(af[cur][mi][2]), "r"(af[cur][mi][3]),
                              "r"(bfr[cur][jp][0]), "r"(bfr[cur][jp][1]));
                        asm volatile("mma.sync.aligned.m16n8k16.row.col.f32.bf16.bf16.f32 "
                            "{%0,%1,%2,%3}, {%4,%5,%6,%7}, {%8,%9}, {%0,%1,%2,%3};"
                            : "+f"(acc[mi][jp * 2 + 1][0]), "+f"(acc[mi][jp * 2 + 1][1]),
                              "+f"(acc[mi][jp * 2 + 1][2]), "+f"(acc[mi][jp * 2 + 1][3])
                            : "r"(af[cur][mi][0]), "r"(af[cur][mi][1]),
                              "r"(af[cur][mi][2]), "r"(af[cur][mi][3]),
                              "r"(bfr[cur][jp][2]), "r"(bfr[cur][jp][3]));
                    }
            }
            __syncthreads();                    // all warps done reading half (nc,h)
            if (nc < 7) loadBhalf(nc + 1, h);
            cp_commit();
        }

        // Epilogue for chunk nc
        int nbase = (nc << 6) + (wn << 5) + (tig << 1);
#pragma unroll
        for (int mi = 0; mi < 2; mi++)
#pragma unroll
            for (int j = 0; j < 4; j++) {
                int cb = nbase + (j << 3);
                float v0 = v_s[cb], v1 = v_s[cb + 1];
                float d0 = dsp_s[cb], d1 = dsp_s[cb + 1];
                lp[mi * 2 + 0] += v0 * tanh_fast(acc[mi][j][0] + d0)
                                + v1 * tanh_fast(acc[mi][j][1] + d1);
                lp[mi * 2 + 1] += v0 * tanh_fast(acc[mi][j][2] + d0)
                                + v1 * tanh_fast(acc[mi][j][3] + d1);
            }
    }

    // Reduce across quad lanes (cols)
#pragma unroll
    for (int q = 0; q < 4; q++) {
        lp[q] += __shfl_xor_sync(0xffffffffu, lp[q], 1);
        lp[q] += __shfl_xor_sync(0xffffffffu, lp[q], 2);
    }
    int row[4];
    row[0] = (wm << 5) + g;
    row[1] = (wm << 5) + 8 + g;
    row[2] = (wm << 5) + 16 + g;
    row[3] = (wm << 5) + 24 + g;
    if (wn == 1 && tig == 0) {
#pragma unroll
        for (int q = 0; q < 4; q++) part[row[q]] = lp[q];
    }
    __syncthreads();
    if (wn == 0 && tig == 0) {
#pragma unroll
        for (int q = 0; q < 4; q++)
            g_l[b * TT + t0 + row[q]] = lp[q] + part[row[q]];
    }
}

// ---------------------------------------------------------------------------
// Kernel 4: softmax over T per batch
// ---------------------------------------------------------------------------
__global__ void k_softmax(float* __restrict__ out) {
    __shared__ float red[8];
    int b = blockIdx.x, tid = threadIdx.x, lane = tid & 31, wid = tid >> 5;
    float vals[8];
    float m = -1e30f;
#pragma unroll
    for (int i = 0; i < 8; i++) {
        vals[i] = g_l[b * TT + i * 256 + tid];
        m = fmaxf(m, vals[i]);
    }
#pragma unroll
    for (int o = 16; o; o >>= 1) m = fmaxf(m, __shfl_xor_sync(0xffffffffu, m, o));
    if (lane == 0) red[wid] = m;
    __syncthreads();
    m = red[0];
#pragma unroll
    for (int i = 1; i < 8; i++) m = fmaxf(m, red[i]);
    __syncthreads();
    float s = 0.f;
#pragma unroll
    for (int i = 0; i < 8; i++) {
        vals[i] = __expf(vals[i] - m);
        s += vals[i];
    }
#pragma unroll
    for (int o = 16; o; o >>= 1) s += __shfl_xor_sync(0xffffffffu, s, o);
    if (lane == 0) red[wid] = s;
    __syncthreads();
    s = 0.f;
#pragma unroll
    for (int i = 0; i < 8; i++) s += red[i];
    float inv = 1.0f / s;
#pragma unroll
    for (int i = 0; i < 8; i++) out[b * TT + i * 256 + tid] = vals[i] * inv;
}

// ---------------------------------------------------------------------------
extern "C" void kernel_launch(void* const* d_in, const int* in_sizes, int n_in,
                              void* d_out, int out_size) {
    const float* h   = (const float*)d_in[0];
    const float* c   = (const float*)d_in[1];
    const float* enc = (const float*)d_in[2];
    const float* W   = (const float*)d_in[3];
    const float* bwd = (const float*)d_in[4];
    const float* U   = (const float*)d_in[5];
    const float* bud = (const float*)d_in[6];
    const float* vd  = (const float*)d_in[7];
    float* out = (float*)d_out;

    cudaFuncSetAttribute(k_main, cudaFuncAttributeMaxDynamicSharedMemorySize, SMEM_TOTAL);

    // k_main 4th -> ncu capture slot
    k_transU<<<dim3(16, 16), dim3(32, 8)>>>(U);
    k_dsproj1<<<128, 512>>>(h, c, W);
    k_dsproj2<<<64, 512>>>(bwd, bud);
    k_main<<<(BB * TT) / 128, 256, SMEM_TOTAL>>>(enc, vd);
    k_softmax<<<BB, 256>>>(out);
}

// round 8
// speedup vs baseline: 1.0579x; 1.0170x over previous
#include <cuda_runtime.h>
#include <cuda_bf16.h>
#include <cstdint>

#define BB 64
#define TT 2048
#define MM 512
#define PP 512

// Device scratch
__device__ float g_part[8 * BB * MM];            // dsproj k-slab partials
__device__ __nv_bfloat16 g_UT[MM * MM];          // U_d^T [n][k], bf16
__device__ float g_l[BB * TT];

__device__ __forceinline__ float tanh_fast(float x) {
    float y;
    asm("tanh.approx.f32 %0, %1;" : "=f"(y) : "f"(x));
    return y;
}
__device__ __forceinline__ void cp_async16(uint32_t dst, const void* src) {
    asm volatile("cp.async.cg.shared.global [%0], [%1], 16;" :: "r"(dst), "l"(src) : "memory");
}
__device__ __forceinline__ void cp_commit() {
    asm volatile("cp.async.commit_group;" ::: "memory");
}
__device__ __forceinline__ void cp_wait1() {
    asm volatile("cp.async.wait_group 1;" ::: "memory");
}

#define SWZ16(r, c) (((r) << 10) + (((c) ^ ((r) & 7)) << 4))

// ---------------------------------------------------------------------------
// Kernel 1 (fused prep): blocks 0-127 compute dsproj k-slab partials,
// blocks 128-191 transpose U to bf16 g_UT (64x64 tiles). 512 threads.
// ---------------------------------------------------------------------------
__global__ __launch_bounds__(512) void k_prep(const float* __restrict__ h,
                                              const float* __restrict__ c,
                                              const float* __restrict__ W,
                                              const float* __restrict__ U) {
    __shared__ float buf[64 * 65];               // transU tile; dsproj uses [0,512)
    int blk = blockIdx.x;
    int tid = threadIdx.x;

    if (blk < 128) {
        // ---- dsproj partials: bgrp = blk>>3 (4 batches), kslab = blk&7 ----
        float (*ds)[128] = (float (*)[128])buf;
        int bgrp = blk >> 3;
        int ks = blk & 7;
        {
            int j = tid >> 7, kk = tid & 127;
            int k = ks * 128 + kk;
            float v = (k < PP) ? h[(bgrp * 4 + j) * PP + k]
                               : c[(bgrp * 4 + j) * PP + (k - PP)];
            ds[j][kk] = v;
        }
        __syncthreads();
        float a0 = 0.f, a1 = 0.f, a2 = 0.f, a3 = 0.f;
        const float* Wp = W + (ks * 128) * MM + tid;
#pragma unroll 8
        for (int kk = 0; kk < 128; kk++) {
            float w = Wp[kk * MM];
            a0 = fmaf(w, ds[0][kk], a0);
            a1 = fmaf(w, ds[1][kk], a1);
            a2 = fmaf(w, ds[2][kk], a2);
            a3 = fmaf(w, ds[3][kk], a3);
        }
        int base = (ks * BB + bgrp * 4) * MM + tid;
        g_part[base] = a0;
        g_part[base + MM] = a1;
        g_part[base + 2 * MM] = a2;
        g_part[base + 3 * MM] = a3;
    } else {
        // ---- transU: 64x64 tile; m = blk-128, n0 = (m&7)*64, k0 = (m>>3)*64
        int m = blk - 128;
        int n0 = (m & 7) << 6;
        int k0 = (m >> 3) << 6;
        int tx = tid & 63, ty = tid >> 6;        // 8 row-strides
#pragma unroll
        for (int i = ty; i < 64; i += 8)
            buf[i * 65 + tx] = U[(k0 + i) * MM + n0 + tx];
        __syncthreads();
#pragma unroll
        for (int i = ty; i < 64; i += 8)
            g_UT[(n0 + i) * MM + (k0 + tx)] = __float2bfloat16(buf[tx * 65 + i]);
    }
}

// ---------------------------------------------------------------------------
// Kernel 2 (k_main, unchanged HMMA-ceiling mainloop): fused GEMM+tanh+v-dot.
// dsproj reduction + biases folded into the prologue (reads g_part).
// ---------------------------------------------------------------------------
#define A_OFF    0
#define B_OFF    131072
#define DSP_OFF  196608
#define V_OFF    198656
#define PART_OFF 200704
#define SMEM_TOTAL 201280

__global__ __launch_bounds__(256, 1) void k_main(const float* __restrict__ enc,
                                                 const float* __restrict__ vd,
                                                 const float* __restrict__ bwd,
                                                 const float* __restrict__ bud) {
    extern __shared__ char sm[];
    uint32_t sbase = (uint32_t)__cvta_generic_to_shared(sm);
    uint32_t sA = sbase + A_OFF;
    uint32_t sB = sbase + B_OFF;
    float* dsp_s = (float*)(sm + DSP_OFF);
    float* v_s = (float*)(sm + V_OFF);
    float* part = (float*)(sm + PART_OFF);

    int blk = blockIdx.x;
    int b = blk >> 4;
    int t0 = (blk & 15) << 7;
    int tid = threadIdx.x;
    int lane = tid & 31;
    int wid = tid >> 5;
    int wm = wid & 3;
    int wn = wid >> 2;
    int g = lane >> 2;
    int tig = lane & 3;

    const __nv_bfloat16* UT = &g_UT[0];

    auto loadBhalf = [&](int nc, int hh) {
        const __nv_bfloat16* srcB = UT + (nc << 6) * MM;
        int cadd = hh << 5;
#pragma unroll
        for (int i = tid; i < 2048; i += 256) {
            int r = i >> 5;
            int c = (i & 31) + cadd;
            cp_async16(sB + SWZ16(r, c), srcB + (r << 9) + (c << 3));
        }
    };

    loadBhalf(0, 0); cp_commit();
    loadBhalf(0, 1); cp_commit();

    // Load A tile + fold dsproj2 (partial reduce + biases) + v
    {
        const float4* src = (const float4*)(enc + (size_t)(b * TT + t0) * MM);
#pragma unroll 8
        for (int i = tid; i < 8192; i += 256) {
            int r = i >> 6;
            int c = i & 63;
            float4 f0 = src[(r << 7) + (c << 1)];
            float4 f1 = src[(r << 7) + (c << 1) + 1];
            __nv_bfloat162 p0 = __floats2bfloat162_rn(f0.x, f0.y);
            __nv_bfloat162 p1 = __floats2bfloat162_rn(f0.z, f0.w);
            __nv_bfloat162 p2 = __floats2bfloat162_rn(f1.x, f1.y);
            __nv_bfloat162 p3 = __floats2bfloat162_rn(f1.z, f1.w);
            uint4 u;
            u.x = *(uint32_t*)&p0; u.y = *(uint32_t*)&p1;
            u.z = *(uint32_t*)&p2; u.w = *(uint32_t*)&p3;
            *(uint4*)(sm + A_OFF + SWZ16(r, c)) = u;
        }
        for (int i = tid; i < MM; i += 256) {
            float s = bwd[i] + bud[i];
#pragma unroll
            for (int ks = 0; ks < 8; ks++)
                s += g_part[(ks * BB + b) * MM + i];
            dsp_s[i] = s;
            v_s[i] = vd[i];
        }
    }

    float lp[4] = {0.f, 0.f, 0.f, 0.f};

    int aRow0 = (wm << 5) + (lane & 15);
    int aRow1 = aRow0 + 16;
    int aCadd = (lane >> 4);
    int bQuad = lane >> 3;
    int bRowIn = lane & 7;
    int bCadd = bQuad & 1;
    int bBlkHalf = bQuad >> 1;
    int bN0 = (wn << 5) + (bBlkHalf << 3) + bRowIn;
    int bN1 = bN0 + 16;

    uint32_t af[2][2][4];
    uint32_t bfr[2][2][4];

    auto loadFrags = [&](int buf, int ks) {
#pragma unroll
        for (int mi = 0; mi < 2; mi++) {
            int r = mi ? aRow1 : aRow0;
            uint32_t addr = sA + SWZ16(r, (ks << 1) + aCadd);
            asm volatile("ldmatrix.sync.aligned.m8n8.x4.shared.b16 {%0,%1,%2,%3}, [%4];"
                         : "=r"(af[buf][mi][0]), "=r"(af[buf][mi][1]),
                           "=r"(af[buf][mi][2]), "=r"(af[buf][mi][3]) : "r"(addr));
        }
#pragma unroll
        for (int jp = 0; jp < 2; jp++) {
            int n = jp ? bN1 : bN0;
            uint32_t addr = sB + SWZ16(n, (ks << 1) + bCadd);
            asm volatile("ldmatrix.sync.aligned.m8n8.x4.shared.b16 {%0,%1,%2,%3}, [%4];"
                         : "=r"(bfr[buf][jp][0]), "=r"(bfr[buf][jp][1]),
                           "=r"(bfr[buf][jp][2]), "=r"(bfr[buf][jp][3]) : "r"(addr));
        }
    };

    float acc[2][4][4];

    for (int nc = 0; nc < 8; nc++) {
#pragma unroll
        for (int mi = 0; mi < 2; mi++)
#pragma unroll
            for (int j = 0; j < 4; j++)
#pragma unroll
                for (int q = 0; q < 4; q++) acc[mi][j][q] = 0.f;

#pragma unroll
        for (int h = 0; h < 2; h++) {
            cp_wait1();
            __syncthreads();
            int kbase = h << 4;

            loadFrags(0, kbase);
#pragma unroll
            for (int kk = 0; kk < 16; kk++) {
                int cur = kk & 1;
                if (kk < 15) loadFrags(cur ^ 1, kbase + kk + 1);
#pragma unroll
                for (int mi = 0; mi < 2; mi++)
#pragma unroll
                    for (int jp = 0; jp < 2; jp++) {
                        asm volatile("mma.sync.aligned.m16n8k16.row.col.f32.bf16.bf16.f32 "
                            "{%0,%1,%2,%3}, {%4,%5,%6,%7}, {%8,%9}, {%0,%1,%2,%3};"
                            : "+f"(acc[mi][jp * 2][0]), "+f"(acc[mi][jp * 2][1]),
                              "+f"(acc[mi][jp * 2][2]), "+f"(acc[mi][jp * 2][3])
                            : "r"(af[cur][mi][0]), "r"(af[cur][mi][1]),
                              "r"(af[cur][mi][2]), "r"(af[cur][mi][3]),
                              "r"(bfr[cur][jp][0]), "r"(bfr[cur][jp][1]));
                        asm volatile("mma.sync.aligned.m16n8k16.row.col.f32.bf16.bf16.f32 "
                            "{%0,%1,%2,%3}, {%4,%5,%6,%7}, {%8,%9}, {%0,%1,%2,%3};"
                            : "+f"(acc[mi][jp * 2 + 1][0]), "+f"(acc[mi][jp * 2 + 1][1]),
                              "+f"(acc[mi][jp * 2 + 1][2]), "+f"(acc[mi][jp * 2 + 1][3])
                            : "r"(af[cur][mi][0]), "r"(af[cur][mi][1]),
                              "r"(af[cur][mi][2]), "r"(af[cur][mi][3]),
                              "r"(bfr[cur][jp][2]), "r"(bfr[cur][jp][3]));
                    }
            }
            __syncthreads();
            if (nc < 7) loadBhalf(nc + 1, h);
            cp_commit();
        }

        int nbase = (nc << 6) + (wn << 5) + (tig << 1);
#pragma unroll
        for (int mi = 0; mi < 2; mi++)
#pragma unroll
            for (int j = 0; j < 4; j++) {
                int cb = nbase + (j << 3);
                float v0 = v_s[cb], v1 = v_s[cb + 1];
                float d0 = dsp_s[cb], d1 = dsp_s[cb + 1];
                lp[mi * 2 + 0] += v0 * tanh_fast(acc[mi][j][0] + d0)
                                + v1 * tanh_fast(acc[mi][j][1] + d1);
                lp[mi * 2 + 1] += v0 * tanh_fast(acc[mi][j][2] + d0)
                                + v1 * tanh_fast(acc[mi][j][3] + d1);
            }
    }

#pragma unroll
    for (int q = 0; q < 4; q++) {
        lp[q] += __shfl_xor_sync(0xffffffffu, lp[q], 1);
        lp[q] += __shfl_xor_sync(0xffffffffu, lp[q], 2);
    }
    int row[4];
    row[0] = (wm << 5) + g;
    row[1] = (wm << 5) + 8 + g;
    row[2] = (wm << 5) + 16 + g;
    row[3] = (wm << 5) + 24 + g;
    if (wn == 1 && tig == 0) {
#pragma unroll
        for (int q = 0; q < 4; q++) part[row[q]] = lp[q];
    }
    __syncthreads();
    if (wn == 0 && tig == 0) {
#pragma unroll
        for (int q = 0; q < 4; q++)
            g_l[b * TT + t0 + row[q]] = lp[q] + part[row[q]];
    }
}

// ---------------------------------------------------------------------------
// Kernel 3: softmax over T per batch. 1024 threads, 2 elements each.
// ---------------------------------------------------------------------------
__global__ __launch_bounds__(1024) void k_softmax(float* __restrict__ out) {
    __shared__ float redm[32];
    __shared__ float reds[32];
    int b = blockIdx.x, tid = threadIdx.x, lane = tid & 31, wid = tid >> 5;
    float v0 = g_l[b * TT + tid];
    float v1 = g_l[b * TT + 1024 + tid];
    float m = fmaxf(v0, v1);
#pragma unroll
    for (int o = 16; o; o >>= 1) m = fmaxf(m, __shfl_xor_sync(0xffffffffu, m, o));
    if (lane == 0) redm[wid] = m;
    __syncthreads();
    if (wid == 0) {
        float mm = redm[lane];
#pragma unroll
        for (int o = 16; o; o >>= 1) mm = fmaxf(mm, __shfl_xor_sync(0xffffffffu, mm, o));
        if (lane == 0) redm[0] = mm;
    }
    __syncthreads();
    m = redm[0];
    float e0 = __expf(v0 - m);
    float e1 = __expf(v1 - m);
    float s = e0 + e1;
#pragma unroll
    for (int o = 16; o; o >>= 1) s += __shfl_xor_sync(0xffffffffu, s, o);
    if (lane == 0) reds[wid] = s;
    __syncthreads();
    if (wid == 0) {
        float ss = reds[lane];
#pragma unroll
        for (int o = 16; o; o >>= 1) ss += __shfl_xor_sync(0xffffffffu, ss, o);
        if (lane == 0) reds[0] = ss;
    }
    __syncthreads();
    float inv = 1.0f / reds[0];
    out[b * TT + tid] = e0 * inv;
    out[b * TT + 1024 + tid] = e1 * inv;
}

// ---------------------------------------------------------------------------
extern "C" void kernel_launch(void* const* d_in, const int* in_sizes, int n_in,
                              void* d_out, int out_size) {
    const float* h   = (const float*)d_in[0];
    const float* c   = (const float*)d_in[1];
    const float* enc = (const float*)d_in[2];
    const float* W   = (const float*)d_in[3];
    const float* bwd = (const float*)d_in[4];
    const float* U   = (const float*)d_in[5];
    const float* bud = (const float*)d_in[6];
    const float* vd  = (const float*)d_in[7];
    float* out = (float*)d_out;

    cudaFuncSetAttribute(k_main, cudaFuncAttributeMaxDynamicSharedMemorySize, SMEM_TOTAL);

    k_prep<<<192, 512>>>(h, c, W, U);
    k_main<<<(BB * TT) / 128, 256, SMEM_TOTAL>>>(enc, vd, bwd, bud);
    k_softmax<<<BB, 1024>>>(out);
}

// round 9
// speedup vs baseline: 1.0915x; 1.0317x over previous
#include <cuda_runtime.h>
#include <cuda_bf16.h>
#include <cstdint>

#define BB 64
#define TT 2048
#define MM 512
#define PP 512

// Device scratch
__device__ float g_part[16 * BB * MM];           // dsproj k-slab partials (16 slabs)
__device__ __nv_bfloat16 g_UT[MM * MM];          // U_d^T [n][k], bf16
__device__ float g_l[BB * TT];

__device__ __forceinline__ float tanh_fast(float x) {
    float y;
    asm("tanh.approx.f32 %0, %1;" : "=f"(y) : "f"(x));
    return y;
}
__device__ __forceinline__ void cp_async16(uint32_t dst, const void* src) {
    asm volatile("cp.async.cg.shared.global [%0], [%1], 16;" :: "r"(dst), "l"(src) : "memory");
}
__device__ __forceinline__ void cp_commit() {
    asm volatile("cp.async.commit_group;" ::: "memory");
}
__device__ __forceinline__ void cp_wait1() {
    asm volatile("cp.async.wait_group 1;" ::: "memory");
}

#define SWZ16(r, c) (((r) << 10) + (((c) ^ ((r) & 7)) << 4))

// ---------------------------------------------------------------------------
// Kernel 1 (fused prep): blocks 0-255 dsproj partials (16 bgrp x 16 kslab,
// slab = 64 k), blocks 256-319 transpose U (64x64 tiles). 512 threads.
// ---------------------------------------------------------------------------
__global__ __launch_bounds__(512) void k_prep(const float* __restrict__ h,
                                              const float* __restrict__ c,
                                              const float* __restrict__ W,
                                              const float* __restrict__ U) {
    __shared__ float buf[64 * 65];
    int blk = blockIdx.x;
    int tid = threadIdx.x;

    if (blk < 256) {
        // ---- dsproj partials: bgrp = blk>>4 (4 batches), kslab = blk&15 ----
        float (*ds)[64] = (float (*)[64])buf;     // [4][64]
        int bgrp = blk >> 4;
        int ks = blk & 15;
        if (tid < 256) {
            int j = tid >> 6, kk = tid & 63;
            int k = ks * 64 + kk;
            ds[j][kk] = (k < PP) ? h[(bgrp * 4 + j) * PP + k]
                                 : c[(bgrp * 4 + j) * PP + (k - PP)];
        }
        __syncthreads();
        float a0 = 0.f, a1 = 0.f, a2 = 0.f, a3 = 0.f;
        const float* Wp = W + (ks * 64) * MM + tid;
#pragma unroll 16
        for (int kk = 0; kk < 64; kk++) {
            float w = Wp[kk * MM];
            a0 = fmaf(w, ds[0][kk], a0);
            a1 = fmaf(w, ds[1][kk], a1);
            a2 = fmaf(w, ds[2][kk], a2);
            a3 = fmaf(w, ds[3][kk], a3);
        }
        int base = (ks * BB + bgrp * 4) * MM + tid;
        g_part[base] = a0;
        g_part[base + MM] = a1;
        g_part[base + 2 * MM] = a2;
        g_part[base + 3 * MM] = a3;
    } else {
        // ---- transU: 64x64 tile; m = blk-256 ----
        int m = blk - 256;
        int n0 = (m & 7) << 6;
        int k0 = (m >> 3) << 6;
        int tx = tid & 63, ty = tid >> 6;
#pragma unroll
        for (int i = ty; i < 64; i += 8)
            buf[i * 65 + tx] = U[(k0 + i) * MM + n0 + tx];
        __syncthreads();
#pragma unroll
        for (int i = ty; i < 64; i += 8)
            g_UT[(n0 + i) * MM + (k0 + tx)] = __float2bfloat16(buf[tx * 65 + i]);
    }
}

// ---------------------------------------------------------------------------
// Kernel 2 (k_main, HMMA-ceiling mainloop): fused GEMM + tanh + v-dot.
// dsproj reduction (16 partials) + biases folded into the prologue.
// ---------------------------------------------------------------------------
#define A_OFF    0
#define B_OFF    131072
#define DSP_OFF  196608
#define V_OFF    198656
#define PART_OFF 200704
#define SMEM_TOTAL 201280

__global__ __launch_bounds__(256, 1) void k_main(const float* __restrict__ enc,
                                                 const float* __restrict__ vd,
                                                 const float* __restrict__ bwd,
                                                 const float* __restrict__ bud) {
    extern __shared__ char sm[];
    uint32_t sbase = (uint32_t)__cvta_generic_to_shared(sm);
    uint32_t sA = sbase + A_OFF;
    uint32_t sB = sbase + B_OFF;
    float* dsp_s = (float*)(sm + DSP_OFF);
    float* v_s = (float*)(sm + V_OFF);
    float* part = (float*)(sm + PART_OFF);

    int blk = blockIdx.x;
    int b = blk >> 4;
    int t0 = (blk & 15) << 7;
    int tid = threadIdx.x;
    int lane = tid & 31;
    int wid = tid >> 5;
    int wm = wid & 3;
    int wn = wid >> 2;
    int g = lane >> 2;
    int tig = lane & 3;

    const __nv_bfloat16* UT = &g_UT[0];

    auto loadBhalf = [&](int nc, int hh) {
        const __nv_bfloat16* srcB = UT + (nc << 6) * MM;
        int cadd = hh << 5;
#pragma unroll
        for (int i = tid; i < 2048; i += 256) {
            int r = i >> 5;
            int c = (i & 31) + cadd;
            cp_async16(sB + SWZ16(r, c), srcB + (r << 9) + (c << 3));
        }
    };

    loadBhalf(0, 0); cp_commit();
    loadBhalf(0, 1); cp_commit();

    // Load A tile + fold dsproj reduce (16 partials + biases) + v
    {
        const float4* src = (const float4*)(enc + (size_t)(b * TT + t0) * MM);
#pragma unroll 8
        for (int i = tid; i < 8192; i += 256) {
            int r = i >> 6;
            int c = i & 63;
            float4 f0 = src[(r << 7) + (c << 1)];
            float4 f1 = src[(r << 7) + (c << 1) + 1];
            __nv_bfloat162 p0 = __floats2bfloat162_rn(f0.x, f0.y);
            __nv_bfloat162 p1 = __floats2bfloat162_rn(f0.z, f0.w);
            __nv_bfloat162 p2 = __floats2bfloat162_rn(f1.x, f1.y);
            __nv_bfloat162 p3 = __floats2bfloat162_rn(f1.z, f1.w);
            uint4 u;
            u.x = *(uint32_t*)&p0; u.y = *(uint32_t*)&p1;
            u.z = *(uint32_t*)&p2; u.w = *(uint32_t*)&p3;
            *(uint4*)(sm + A_OFF + SWZ16(r, c)) = u;
        }
        for (int i = tid; i < MM; i += 256) {
            float s = bwd[i] + bud[i];
#pragma unroll
            for (int ks = 0; ks < 16; ks++)
                s += g_part[(ks * BB + b) * MM + i];
            dsp_s[i] = s;
            v_s[i] = vd[i];
        }
    }

    float lp[4] = {0.f, 0.f, 0.f, 0.f};

    int aRow0 = (wm << 5) + (lane & 15);
    int aRow1 = aRow0 + 16;
    int aCadd = (lane >> 4);
    int bQuad = lane >> 3;
    int bRowIn = lane & 7;
    int bCadd = bQuad & 1;
    int bBlkHalf = bQuad >> 1;
    int bN0 = (wn << 5) + (bBlkHalf << 3) + bRowIn;
    int bN1 = bN0 + 16;

    uint32_t af[2][2][4];
    uint32_t bfr[2][2][4];

    auto loadFrags = [&](int buf, int ks) {
#pragma unroll
        for (int mi = 0; mi < 2; mi++) {
            int r = mi ? aRow1 : aRow0;
            uint32_t addr = sA + SWZ16(r, (ks << 1) + aCadd);
            asm volatile("ldmatrix.sync.aligned.m8n8.x4.shared.b16 {%0,%1,%2,%3}, [%4];"
                         : "=r"(af[buf][mi][0]), "=r"(af[buf][mi][1]),
                           "=r"(af[buf][mi][2]), "=r"(af[buf][mi][3]) : "r"(addr));
        }
#pragma unroll
        for (int jp = 0; jp < 2; jp++) {
            int n = jp ? bN1 : bN0;
            uint32_t addr = sB + SWZ16(n, (ks << 1) + bCadd);
            asm volatile("ldmatrix.sync.aligned.m8n8.x4.shared.b16 {%0,%1,%2,%3}, [%4];"
                         : "=r"(bfr[buf][jp][0]), "=r"(bfr[buf][jp][1]),
                           "=r"(bfr[buf][jp][2]), "=r"(bfr[buf][jp][3]) : "r"(addr));
        }
    };

    float acc[2][4][4];

    for (int nc = 0; nc < 8; nc++) {
#pragma unroll
        for (int mi = 0; mi < 2; mi++)
#pragma unroll
            for (int j = 0; j < 4; j++)
#pragma unroll
                for (int q = 0; q < 4; q++) acc[mi][j][q] = 0.f;

#pragma unroll
        for (int h = 0; h < 2; h++) {
            cp_wait1();
            __syncthreads();
            int kbase = h << 4;

            loadFrags(0, kbase);
#pragma unroll
            for (int kk = 0; kk < 16; kk++) {
                int cur = kk & 1;
                if (kk < 15) loadFrags(cur ^ 1, kbase + kk + 1);
#pragma unroll
                for (int mi = 0; mi < 2; mi++)
#pragma unroll
                    for (int jp = 0; jp < 2; jp++) {
                        asm volatile("mma.sync.aligned.m16n8k16.row.col.f32.bf16.bf16.f32 "
                            "{%0,%1,%2,%3}, {%4,%5,%6,%7}, {%8,%9}, {%0,%1,%2,%3};"
                            : "+f"(acc[mi][jp * 2][0]), "+f"(acc[mi][jp * 2][1]),
                              "+f"(acc[mi][jp * 2][2]), "+f"(acc[mi][jp * 2][3])
                            : "r"(af[cur][mi][0]), "r"(af[cur][mi][1]),
                              "r"(af[cur][mi][2]), "r"(af[cur][mi][3]),
                              "r"(bfr[cur][jp][0]), "r"(bfr[cur][jp][1]));
                        asm volatile("mma.sync.aligned.m16n8k16.row.col.f32.bf16.bf16.f32 "
                            "{%0,%1,%2,%3}, {%4,%5,%6,%7}, {%8,%9}, {%0,%1,%2,%3};"
                            : "+f"(acc[mi][jp * 2 + 1][0]), "+f"(acc[mi][jp * 2 + 1][1]),
                              "+f"(acc[mi][jp * 2 + 1][2]), "+f"(acc[mi][jp * 2 + 1][3])
                            : "r"(af[cur][mi][0]), "r"(af[cur][mi][1]),
                              "r"(af[cur][mi][2]), "r"(af[cur][mi][3]),
                              "r"(bfr[cur][jp][2]), "r"(bfr[cur][jp][3]));
                    }
            }
            __syncthreads();
            if (nc < 7) loadBhalf(nc + 1, h);
            cp_commit();
        }

        int nbase = (nc << 6) + (wn << 5) + (tig << 1);
#pragma unroll
        for (int mi = 0; mi < 2; mi++)
#pragma unroll
            for (int j = 0; j < 4; j++) {
                int cb = nbase + (j << 3);
                float v0 = v_s[cb], v1 = v_s[cb + 1];
                float d0 = dsp_s[cb], d1 = dsp_s[cb + 1];
                lp[mi * 2 + 0] += v0 * tanh_fast(acc[mi][j][0] + d0)
                                + v1 * tanh_fast(acc[mi][j][1] + d1);
                lp[mi * 2 + 1] += v0 * tanh_fast(acc[mi][j][2] + d0)
                                + v1 * tanh_fast(acc[mi][j][3] + d1);
            }
    }

#pragma unroll
    for (int q = 0; q < 4; q++) {
        lp[q] += __shfl_xor_sync(0xffffffffu, lp[q], 1);
        lp[q] += __shfl_xor_sync(0xffffffffu, lp[q], 2);
    }
    int row[4];
    row[0] = (wm << 5) + g;
    row[1] = (wm << 5) + 8 + g;
    row[2] = (wm << 5) + 16 + g;
    row[3] = (wm << 5) + 24 + g;
    if (wn == 1 && tig == 0) {
#pragma unroll
        for (int q = 0; q < 4; q++) part[row[q]] = lp[q];
    }
    __syncthreads();
    if (wn == 0 && tig == 0) {
#pragma unroll
        for (int q = 0; q < 4; q++)
            g_l[b * TT + t0 + row[q]] = lp[q] + part[row[q]];
    }
}

// ---------------------------------------------------------------------------
// Kernel 3: softmax over T per batch. 1024 threads, 2 elements each.
// ---------------------------------------------------------------------------
__global__ __launch_bounds__(1024) void k_softmax(float* __restrict__ out) {
    __shared__ float redm[32];
    __shared__ float reds[32];
    int b = blockIdx.x, tid = threadIdx.x, lane = tid & 31, wid = tid >> 5;
    float v0 = g_l[b * TT + tid];
    float v1 = g_l[b * TT + 1024 + tid];
    float m = fmaxf(v0, v1);
#pragma unroll
    for (int o = 16; o; o >>= 1) m = fmaxf(m, __shfl_xor_sync(0xffffffffu, m, o));
    if (lane == 0) redm[wid] = m;
    __syncthreads();
    if (wid == 0) {
        float mm = redm[lane];
#pragma unroll
        for (int o = 16; o; o >>= 1) mm = fmaxf(mm, __shfl_xor_sync(0xffffffffu, mm, o));
        if (lane == 0) redm[0] = mm;
    }
    __syncthreads();
    m = redm[0];
    float e0 = __expf(v0 - m);
    float e1 = __expf(v1 - m);
    float s = e0 + e1;
#pragma unroll
    for (int o = 16; o; o >>= 1) s += __shfl_xor_sync(0xffffffffu, s, o);
    if (lane == 0) reds[wid] = s;
    __syncthreads();
    if (wid == 0) {
        float ss = reds[lane];
#pragma unroll
        for (int o = 16; o; o >>= 1) ss += __shfl_xor_sync(0xffffffffu, ss, o);
        if (lane == 0) reds[0] = ss;
    }
    __syncthreads();
    float inv = 1.0f / reds[0];
    out[b * TT + tid] = e0 * inv;
    out[b * TT + 1024 + tid] = e1 * inv;
}

// ---------------------------------------------------------------------------
extern "C" void kernel_launch(void* const* d_in, const int* in_sizes, int n_in,
                              void* d_out, int out_size) {
    const float* h   = (const float*)d_in[0];
    const float* c   = (const float*)d_in[1];
    const float* enc = (const float*)d_in[2];
    const float* W   = (const float*)d_in[3];
    const float* bwd = (const float*)d_in[4];
    const float* U   = (const float*)d_in[5];
    const float* bud = (const float*)d_in[6];
    const float* vd  = (const float*)d_in[7];
    float* out = (float*)d_out;

    cudaFuncSetAttribute(k_main, cudaFuncAttributeMaxDynamicSharedMemorySize, SMEM_TOTAL);

    k_prep<<<320, 512>>>(h, c, W, U);
    k_main<<<(BB * TT) / 128, 256, SMEM_TOTAL>>>(enc, vd, bwd, bud);
    k_softmax<<<BB, 1024>>>(out);
}